// round 13
// baseline (speedup 1.0000x reference)
#include <cuda_runtime.h>
#include <cstdint>
#include <math.h>

#define Bb 8
#define Tt 2048
#define Ee 1024
#define Hd 128
#define NROW (Bb * Tt)

// Scratch (__device__ globals per allocation rules).
__device__ float g_Q[NROW * Hd];
__device__ float g_K[NROW * Hd];
__device__ float g_V[NROW * Hd];

__device__ __forceinline__ float tf32r(float x) {
    float r;
    asm("cvt.rna.tf32.f32 %0, %1;" : "=f"(r) : "f"(x));
    return r;
}

// mma.sync m16n8k8 tf32: D = A*B + C (C==D registers)
__device__ __forceinline__ void mma8(float c[4], uint32_t a0, uint32_t a1,
                                     uint32_t a2, uint32_t a3,
                                     uint32_t b0, uint32_t b1) {
    asm volatile(
        "mma.sync.aligned.m16n8k8.row.col.f32.tf32.tf32.f32 "
        "{%0,%1,%2,%3}, {%4,%5,%6,%7}, {%8,%9}, {%0,%1,%2,%3};"
        : "+f"(c[0]), "+f"(c[1]), "+f"(c[2]), "+f"(c[3])
        : "r"(a0), "r"(a1), "r"(a2), "r"(a3), "r"(b0), "r"(b1));
}

// ===========================================================================
// Kernel 1: QKV projection, fp32. 64-row m-tiles (grid 256x3 = 768 jobs),
// 4x8 microtile, occupancy 3 -> ~444 concurrent lanes, balanced tail.
// ===========================================================================
__global__ __launch_bounds__(256, 3) void qkv_kernel(
    const float* __restrict__ x,
    const float* __restrict__ Wq,
    const float* __restrict__ Wk,
    const float* __restrict__ Wv)
{
    __shared__ float As[2][8][64];   // [buf][k][row]
    __shared__ float Bs[2][8][128];  // [buf][k][col]

    const int which = blockIdx.y;
    const float* __restrict__ W = (which == 0) ? Wq : ((which == 1) ? Wk : Wv);
    float* __restrict__ out = (which == 0) ? g_Q : ((which == 1) ? g_K : g_V);

    const int tid = threadIdx.x;
    const int tx = tid & 15;
    const int ty = tid >> 4;            // 0..15 -> rows ty*4..+3 (64 rows)
    const int m0 = blockIdx.x * 64;

    const int arow = tid >> 1;          // 0..127 (only tid<128 valid: rows 0..63)
    const int acol = (tid & 1) * 4;
    const int brow = tid >> 5;          // 0..7
    const int bcol = (tid & 31) * 4;

    const float* xg = x + (size_t)(m0 + arow) * Ee + acol;
    const float* wg = W + (size_t)brow * Hd + bcol;

    float acc[4][8];
#pragma unroll
    for (int i = 0; i < 4; ++i)
#pragma unroll
        for (int j = 0; j < 8; ++j) acc[i][j] = 0.0f;

    // preload tile 0
    if (tid < 128) {
        float4 a = *(const float4*)xg;
        As[0][acol + 0][arow] = a.x;
        As[0][acol + 1][arow] = a.y;
        As[0][acol + 2][arow] = a.z;
        As[0][acol + 3][arow] = a.w;
    }
    {
        float4 bv = *(const float4*)wg;
        *(float4*)&Bs[0][brow][bcol] = bv;
    }
    __syncthreads();

    int buf = 0;
    const int NT = Ee / 8;
    for (int t = 0; t < NT; ++t) {
        float4 a2, b2;
        if (t < NT - 1) {
            if (tid < 128) a2 = *(const float4*)(xg + (size_t)(t + 1) * 8);
            b2 = *(const float4*)(wg + (size_t)(t + 1) * 8 * Hd);
        }
#pragma unroll
        for (int k = 0; k < 8; ++k) {
            float4 a0 = *(const float4*)&As[buf][k][ty * 4];
            float4 b0 = *(const float4*)&Bs[buf][k][tx * 4];
            float4 b1 = *(const float4*)&Bs[buf][k][64 + tx * 4];
            float af[4] = {a0.x, a0.y, a0.z, a0.w};
            float bf[8] = {b0.x, b0.y, b0.z, b0.w, b1.x, b1.y, b1.z, b1.w};
#pragma unroll
            for (int i = 0; i < 4; ++i)
#pragma unroll
                for (int j = 0; j < 8; ++j)
                    acc[i][j] = fmaf(af[i], bf[j], acc[i][j]);
        }
        if (t < NT - 1) {
            buf ^= 1;
            if (tid < 128) {
                As[buf][acol + 0][arow] = a2.x;
                As[buf][acol + 1][arow] = a2.y;
                As[buf][acol + 2][arow] = a2.z;
                As[buf][acol + 3][arow] = a2.w;
            }
            *(float4*)&Bs[buf][brow][bcol] = b2;
        }
        __syncthreads();
    }

#pragma unroll
    for (int i = 0; i < 4; ++i) {
        int row = m0 + ty * 4 + i;
        float* op = out + (size_t)row * Hd;
        float4 v0 = make_float4(acc[i][0], acc[i][1], acc[i][2], acc[i][3]);
        float4 v1 = make_float4(acc[i][4], acc[i][5], acc[i][6], acc[i][7]);
        *(float4*)&op[tx * 4] = v0;
        *(float4*)&op[64 + tx * 4] = v1;
    }
}

// ===========================================================================
// Kernel 2: flash attention on mma.sync tf32 with LAZY CORRECTION:
// pass 1 computes S with hi*hi only (64 mma, ~0.5 abs err post-scale) for the
// dead test; only live tiles add the Ah*Bl + Al*Bh corrections (128 mma).
// Approx row-max serves as the softmax reference (exp <= e^0.5, safe).
// scale is folded into Q at load. 256 thr = 4 q-groups x 2 key-halves;
// independent per-half online softmax, split-KV merge in epilogue.
// ===========================================================================
#define QKSTR 132   // Q/K row stride (floats)
#define VPSTR 68    // V^T / P row stride (floats)

#define SM_QH 0
#define SM_QL (SM_QH + 64 * QKSTR)
#define SM_KH (SM_QL + 64 * QKSTR)
#define SM_KL (SM_KH + 64 * QKSTR)
#define SM_VH (SM_KL + 64 * QKSTR)
#define SM_PH (SM_VH + 128 * VPSTR)
#define SM_MM (SM_PH + 64 * VPSTR)
#define SM_LL (SM_MM + 64)
#define ATTN_SMEM_FLOATS (SM_LL + 64)
#define ATTN_SMEM_BYTES (ATTN_SMEM_FLOATS * 4)

__global__ __launch_bounds__(256, 1) void attn_kernel(float* __restrict__ out)
{
    extern __shared__ float sm[];
    float* Qh = sm + SM_QH;
    float* Ql = sm + SM_QL;
    float* Kh = sm + SM_KH;
    float* Kl = sm + SM_KL;
    float* Vh = sm + SM_VH;   // transposed [h][key]
    float* Ph = sm + SM_PH;   // [q][key], tf32-rounded
    float* MM = sm + SM_MM;
    float* LL = sm + SM_LL;

    const int tid = threadIdx.x;
    const int w = tid >> 5;
    const int lane = tid & 31;
    const int g = lane >> 2;
    const int tig = lane & 3;
    const int qgrp = w & 3;
    const int khalf = w >> 2;
    const int kofs = 32 * khalf;
    const int b = blockIdx.y;
    const float scale = 45.25483399593904f;  // sqrt(2048), folded into Q

    const int qrow0 = 16 * qgrp + g;
    const int aQ0 = qrow0 * QKSTR;
    const int aQ1 = (qrow0 + 8) * QKSTR;

    for (int half = 0; half < 2; ++half) {
        const int qt = half ? (31 - (int)blockIdx.x) : (int)blockIdx.x;

        __syncthreads();  // all smem (incl. epilogue buffers) reusable

        // ---- load Q tile [64][128], scale folded in, split hi/lo ----
        {
            const float* Qg = g_Q + ((size_t)(b * Tt) + qt * 64) * Hd;
#pragma unroll
            for (int it = 0; it < 8; ++it) {
                int fid = it * 256 + tid;
                int r = fid >> 5;
                int c = (fid & 31) << 2;
                float4 v = *(const float4*)&Qg[(size_t)r * Hd + c];
                v.x *= scale; v.y *= scale; v.z *= scale; v.w *= scale;
                float4 hi = make_float4(tf32r(v.x), tf32r(v.y), tf32r(v.z), tf32r(v.w));
                float4 lo = make_float4(tf32r(v.x - hi.x), tf32r(v.y - hi.y),
                                        tf32r(v.z - hi.z), tf32r(v.w - hi.w));
                *(float4*)&Qh[r * QKSTR + c] = hi;
                *(float4*)&Ql[r * QKSTR + c] = lo;
            }
        }

        float m0 = -INFINITY, m1 = -INFINITY, l0 = 0.0f, l1 = 0.0f;
        float O[16][4];
#pragma unroll
        for (int a = 0; a < 16; ++a)
#pragma unroll
            for (int j = 0; j < 4; ++j) O[a][j] = 0.0f;

        for (int kt = 0; kt <= qt; ++kt) {
            __syncthreads();  // prev compute done: K/V buffers reusable; Q visible

            // ---- load K tile [64][128] hi/lo and V tile transposed (hi only) ----
            {
                const float* Kg = g_K + ((size_t)(b * Tt) + kt * 64) * Hd;
                const float* Vg = g_V + ((size_t)(b * Tt) + kt * 64) * Hd;
#pragma unroll
                for (int it = 0; it < 8; ++it) {
                    int fid = it * 256 + tid;
                    {   // K: coalesced read, row-major padded store
                        int r = fid >> 5;
                        int c = (fid & 31) << 2;
                        float4 v = *(const float4*)&Kg[(size_t)r * Hd + c];
                        float4 hi = make_float4(tf32r(v.x), tf32r(v.y), tf32r(v.z), tf32r(v.w));
                        float4 lo = make_float4(tf32r(v.x - hi.x), tf32r(v.y - hi.y),
                                                tf32r(v.z - hi.z), tf32r(v.w - hi.w));
                        *(float4*)&Kh[r * QKSTR + c] = hi;
                        *(float4*)&Kl[r * QKSTR + c] = lo;
                    }
                    {   // V: transposed store, tf32 hi only
                        int r = fid & 63;          // key
                        int c = (fid >> 6) << 2;   // h chunk
                        float4 v = *(const float4*)&Vg[(size_t)r * Hd + c];
                        Vh[(c + 0) * VPSTR + r] = tf32r(v.x);
                        Vh[(c + 1) * VPSTR + r] = tf32r(v.y);
                        Vh[(c + 2) * VPSTR + r] = tf32r(v.z);
                        Vh[(c + 3) * VPSTR + r] = tf32r(v.w);
                    }
                }
            }
            __syncthreads();

            // ---- pass 1: S approx = Qh Kh^T (hi*hi only) ----
            float sc[4][4];
#pragma unroll
            for (int a = 0; a < 4; ++a)
#pragma unroll
                for (int j = 0; j < 4; ++j) sc[a][j] = 0.0f;

#pragma unroll
            for (int ks = 0; ks < 16; ++ks) {
                const int kb = ks * 8;
                uint32_t ah0 = __float_as_uint(Qh[aQ0 + kb + tig]);
                uint32_t ah1 = __float_as_uint(Qh[aQ1 + kb + tig]);
                uint32_t ah2 = __float_as_uint(Qh[aQ0 + kb + tig + 4]);
                uint32_t ah3 = __float_as_uint(Qh[aQ1 + kb + tig + 4]);
#pragma unroll
                for (int a = 0; a < 4; ++a) {
                    const int kr = (kofs + 8 * a + g) * QKSTR + kb;
                    uint32_t bh0 = __float_as_uint(Kh[kr + tig]);
                    uint32_t bh1 = __float_as_uint(Kh[kr + tig + 4]);
                    mma8(sc[a], ah0, ah1, ah2, ah3, bh0, bh1);
                }
            }

            // ---- causal mask (scale already folded into Q) ----
            const int qg0 = qt * 64 + qrow0;
            const int qg1 = qg0 + 8;
#pragma unroll
            for (int a = 0; a < 4; ++a) {
                const int col = kt * 64 + kofs + 8 * a + 2 * tig;
                if (col     > qg0) sc[a][0] = -INFINITY;
                if (col + 1 > qg0) sc[a][1] = -INFINITY;
                if (col     > qg1) sc[a][2] = -INFINITY;
                if (col + 1 > qg1) sc[a][3] = -INFINITY;
            }

            // ---- approx row maxima (4-lane groups) ----
            float r0 = fmaxf(fmaxf(sc[0][0], sc[0][1]), fmaxf(sc[1][0], sc[1][1]));
            r0 = fmaxf(r0, fmaxf(fmaxf(sc[2][0], sc[2][1]), fmaxf(sc[3][0], sc[3][1])));
            float r1 = fmaxf(fmaxf(sc[0][2], sc[0][3]), fmaxf(sc[1][2], sc[1][3]));
            r1 = fmaxf(r1, fmaxf(fmaxf(sc[2][2], sc[2][3]), fmaxf(sc[3][2], sc[3][3])));
#pragma unroll
            for (int off = 1; off <= 2; off <<= 1) {
                r0 = fmaxf(r0, __shfl_xor_sync(0xffffffffu, r0, off));
                r1 = fmaxf(r1, __shfl_xor_sync(0xffffffffu, r1, off));
            }

            // ---- warp-local dead skip (margin 72: 80 minus approx error) ----
            bool dead = (r0 <= m0 - 72.0f) && (r1 <= m1 - 72.0f);
            if (__all_sync(0xffffffffu, dead)) continue;

            // ---- pass 2 (live only): corrections Ah*Bl + Al*Bh ----
#pragma unroll
            for (int ks = 0; ks < 16; ++ks) {
                const int kb = ks * 8;
                uint32_t ah0 = __float_as_uint(Qh[aQ0 + kb + tig]);
                uint32_t ah1 = __float_as_uint(Qh[aQ1 + kb + tig]);
                uint32_t ah2 = __float_as_uint(Qh[aQ0 + kb + tig + 4]);
                uint32_t ah3 = __float_as_uint(Qh[aQ1 + kb + tig + 4]);
                uint32_t al0 = __float_as_uint(Ql[aQ0 + kb + tig]);
                uint32_t al1 = __float_as_uint(Ql[aQ1 + kb + tig]);
                uint32_t al2 = __float_as_uint(Ql[aQ0 + kb + tig + 4]);
                uint32_t al3 = __float_as_uint(Ql[aQ1 + kb + tig + 4]);
#pragma unroll
                for (int a = 0; a < 4; ++a) {
                    const int kr = (kofs + 8 * a + g) * QKSTR + kb;
                    uint32_t bh0 = __float_as_uint(Kh[kr + tig]);
                    uint32_t bh1 = __float_as_uint(Kh[kr + tig + 4]);
                    uint32_t bl0 = __float_as_uint(Kl[kr + tig]);
                    uint32_t bl1 = __float_as_uint(Kl[kr + tig + 4]);
                    mma8(sc[a], ah0, ah1, ah2, ah3, bl0, bl1);
                    mma8(sc[a], al0, al1, al2, al3, bh0, bh1);
                }
            }

            // ---- online softmax using approx maxima as reference ----
            // clamp so fully-masked rows never produce -inf - -inf = NaN
            float mn0 = fmaxf(fmaxf(m0, r0), -1e30f);
            float mn1 = fmaxf(fmaxf(m1, r1), -1e30f);
            float al_0 = __expf(m0 - mn0);
            float al_1 = __expf(m1 - mn1);
            float ls0 = 0.0f, ls1 = 0.0f;
#pragma unroll
            for (int a = 0; a < 4; ++a) {
                float p00 = __expf(sc[a][0] - mn0);
                float p01 = __expf(sc[a][1] - mn0);
                float p10 = __expf(sc[a][2] - mn1);
                float p11 = __expf(sc[a][3] - mn1);
                ls0 += p00 + p01;
                ls1 += p10 + p11;
                const int col = kofs + 8 * a + 2 * tig;
                Ph[qrow0 * VPSTR + col] = tf32r(p00);
                Ph[qrow0 * VPSTR + col + 1] = tf32r(p01);
                Ph[(qrow0 + 8) * VPSTR + col] = tf32r(p10);
                Ph[(qrow0 + 8) * VPSTR + col + 1] = tf32r(p11);
            }
#pragma unroll
            for (int off = 1; off <= 2; off <<= 1) {
                ls0 += __shfl_xor_sync(0xffffffffu, ls0, off);
                ls1 += __shfl_xor_sync(0xffffffffu, ls1, off);
            }
            l0 = l0 * al_0 + ls0;
            l1 = l1 * al_1 + ls1;
            m0 = mn0;
            m1 = mn1;

#pragma unroll
            for (int a = 0; a < 16; ++a) {
                O[a][0] *= al_0; O[a][1] *= al_0;
                O[a][2] *= al_1; O[a][3] *= al_1;
            }

            __syncwarp();  // P block is warp-private; order STS before LDS

            // ---- O_half += P(:, half) V(half, :)  (hi product only) ----
#pragma unroll
            for (int ks = 0; ks < 4; ++ks) {
                const int kb = kofs + ks * 8;
                uint32_t a0 = __float_as_uint(Ph[qrow0 * VPSTR + kb + tig]);
                uint32_t a1 = __float_as_uint(Ph[(qrow0 + 8) * VPSTR + kb + tig]);
                uint32_t a2 = __float_as_uint(Ph[qrow0 * VPSTR + kb + tig + 4]);
                uint32_t a3 = __float_as_uint(Ph[(qrow0 + 8) * VPSTR + kb + tig + 4]);
#pragma unroll
                for (int a = 0; a < 16; ++a) {
                    const int vr = (8 * a + g) * VPSTR + kb;
                    uint32_t bh0 = __float_as_uint(Vh[vr + tig]);
                    uint32_t bh1 = __float_as_uint(Vh[vr + tig + 4]);
                    mma8(O[a], a0, a1, a2, a3, bh0, bh1);
                }
            }
        }

        // ---- epilogue: split-KV merge of the two key-halves ----
        __syncthreads();           // mainloop reads of Kh done
        float* Obuf = Kh;          // reuse [64][132]
        if (khalf == 1) {
#pragma unroll
            for (int a = 0; a < 16; ++a) {
                const int colc = 8 * a + 2 * tig;
                *(float2*)&Obuf[qrow0 * QKSTR + colc] = make_float2(O[a][0], O[a][1]);
                *(float2*)&Obuf[(qrow0 + 8) * QKSTR + colc] = make_float2(O[a][2], O[a][3]);
            }
            if (tig == 0) {
                MM[qrow0] = m0; LL[qrow0] = l0;
                MM[qrow0 + 8] = m1; LL[qrow0 + 8] = l1;
            }
        }
        __syncthreads();
        if (khalf == 0) {
            const float m1r = MM[qrow0],     l1r = LL[qrow0];
            const float m3r = MM[qrow0 + 8], l3r = LL[qrow0 + 8];
            const float mf0 = fmaxf(m0, m1r);
            const float mf1 = fmaxf(m1, m3r);
            const float w00 = __expf(m0 - mf0), w01 = __expf(m1r - mf0);
            const float w10 = __expf(m1 - mf1), w11 = __expf(m3r - mf1);
            const float inv0 = 1.0f / (l0 * w00 + l1r * w01);
            const float inv1 = 1.0f / (l1 * w10 + l3r * w11);
            const int q0 = qt * 64 + qrow0;
            float* op0 = out + ((size_t)(b * Tt) + q0) * Hd;
            float* op1 = op0 + 8 * Hd;
#pragma unroll
            for (int a = 0; a < 16; ++a) {
                const int colc = 8 * a + 2 * tig;
                float2 e0 = *(float2*)&Obuf[qrow0 * QKSTR + colc];
                float2 e1 = *(float2*)&Obuf[(qrow0 + 8) * QKSTR + colc];
                *(float2*)&op0[colc] =
                    make_float2((O[a][0] * w00 + e0.x * w01) * inv0,
                                (O[a][1] * w00 + e0.y * w01) * inv0);
                *(float2*)&op1[colc] =
                    make_float2((O[a][2] * w10 + e1.x * w11) * inv1,
                                (O[a][3] * w10 + e1.y * w11) * inv1);
            }
        }
    }
}

// ===========================================================================

extern "C" void kernel_launch(void* const* d_in, const int* in_sizes, int n_in,
                              void* d_out, int out_size)
{
    const float* x  = (const float*)d_in[0];
    const float* Wq = (const float*)d_in[1];
    const float* Wk = (const float*)d_in[2];
    const float* Wv = (const float*)d_in[3];
    float* out = (float*)d_out;

    dim3 g1(NROW / 64, 3);   // 256 x 3 = 768 jobs, occupancy 3
    qkv_kernel<<<g1, 256>>>(x, Wq, Wk, Wv);

    cudaFuncSetAttribute(attn_kernel, cudaFuncAttributeMaxDynamicSharedMemorySize,
                         ATTN_SMEM_BYTES);
    dim3 g2(16, Bb);
    attn_kernel<<<g2, 256, ATTN_SMEM_BYTES>>>(out);
}

// round 14
// speedup vs baseline: 1.2866x; 1.2866x over previous
#include <cuda_runtime.h>
#include <cstdint>
#include <math.h>

#define Bb 8
#define Tt 2048
#define Ee 1024
#define Hd 128
#define NROW (Bb * Tt)

// Scratch (__device__ globals per allocation rules).
__device__ float g_Q[NROW * Hd];
__device__ float g_K[NROW * Hd];
__device__ float g_V[NROW * Hd];

__device__ __forceinline__ float tf32r(float x) {
    float r;
    asm("cvt.rna.tf32.f32 %0, %1;" : "=f"(r) : "f"(x));
    return r;
}

// mma.sync m16n8k8 tf32: D = A*B + C (C==D registers)
__device__ __forceinline__ void mma8(float c[4], uint32_t a0, uint32_t a1,
                                     uint32_t a2, uint32_t a3,
                                     uint32_t b0, uint32_t b1) {
    asm volatile(
        "mma.sync.aligned.m16n8k8.row.col.f32.tf32.tf32.f32 "
        "{%0,%1,%2,%3}, {%4,%5,%6,%7}, {%8,%9}, {%0,%1,%2,%3};"
        : "+f"(c[0]), "+f"(c[1]), "+f"(c[2]), "+f"(c[3])
        : "r"(a0), "r"(a1), "r"(a2), "r"(a3), "r"(b0), "r"(b1));
}

__device__ __forceinline__ uint32_t smem_u32(const void* p) {
    uint32_t a;
    asm("{ .reg .u64 t; cvta.to.shared.u64 t, %1; cvt.u32.u64 %0, t; }"
        : "=r"(a) : "l"(p));
    return a;
}
__device__ __forceinline__ void cp16(uint32_t saddr, const void* g) {
    asm volatile("cp.async.cg.shared.global [%0], [%1], 16;"
                 :: "r"(saddr), "l"(g) : "memory");
}
#define CP_COMMIT() asm volatile("cp.async.commit_group;" ::: "memory")
#define CP_WAIT0()  asm volatile("cp.async.wait_group 0;" ::: "memory")

// ===========================================================================
// Kernel 1: QKV projection, fp32 (round-12 proven, ~96% of FFMA ceiling).
// ===========================================================================
__global__ __launch_bounds__(256, 2) void qkv_kernel(
    const float* __restrict__ x,
    const float* __restrict__ Wq,
    const float* __restrict__ Wk,
    const float* __restrict__ Wv)
{
    __shared__ float As[2][8][128];
    __shared__ float Bs[2][8][128];

    const int which = blockIdx.y;
    const float* __restrict__ W = (which == 0) ? Wq : ((which == 1) ? Wk : Wv);
    float* __restrict__ out = (which == 0) ? g_Q : ((which == 1) ? g_K : g_V);

    const int tid = threadIdx.x;
    const int tx = tid & 15;
    const int ty = tid >> 4;
    const int m0 = blockIdx.x * 128;

    const int arow = tid >> 1;
    const int acol = (tid & 1) * 4;
    const int brow = tid >> 5;
    const int bcol = (tid & 31) * 4;

    const float* xg = x + (size_t)(m0 + arow) * Ee + acol;
    const float* wg = W + (size_t)brow * Hd + bcol;

    float acc[8][8];
#pragma unroll
    for (int i = 0; i < 8; ++i)
#pragma unroll
        for (int j = 0; j < 8; ++j) acc[i][j] = 0.0f;

    {
        float4 a = *(const float4*)xg;
        float4 bv = *(const float4*)wg;
        As[0][acol + 0][arow] = a.x;
        As[0][acol + 1][arow] = a.y;
        As[0][acol + 2][arow] = a.z;
        As[0][acol + 3][arow] = a.w;
        *(float4*)&Bs[0][brow][bcol] = bv;
    }
    __syncthreads();

    int buf = 0;
    const int NT = Ee / 8;
    for (int t = 0; t < NT; ++t) {
        float4 a2, b2;
        if (t < NT - 1) {
            a2 = *(const float4*)(xg + (size_t)(t + 1) * 8);
            b2 = *(const float4*)(wg + (size_t)(t + 1) * 8 * Hd);
        }
#pragma unroll
        for (int k = 0; k < 8; ++k) {
            float4 a0 = *(const float4*)&As[buf][k][ty * 4];
            float4 a1 = *(const float4*)&As[buf][k][64 + ty * 4];
            float4 b0 = *(const float4*)&Bs[buf][k][tx * 4];
            float4 b1 = *(const float4*)&Bs[buf][k][64 + tx * 4];
            float af[8] = {a0.x, a0.y, a0.z, a0.w, a1.x, a1.y, a1.z, a1.w};
            float bf[8] = {b0.x, b0.y, b0.z, b0.w, b1.x, b1.y, b1.z, b1.w};
#pragma unroll
            for (int i = 0; i < 8; ++i)
#pragma unroll
                for (int j = 0; j < 8; ++j)
                    acc[i][j] = fmaf(af[i], bf[j], acc[i][j]);
        }
        if (t < NT - 1) {
            buf ^= 1;
            As[buf][acol + 0][arow] = a2.x;
            As[buf][acol + 1][arow] = a2.y;
            As[buf][acol + 2][arow] = a2.z;
            As[buf][acol + 3][arow] = a2.w;
            *(float4*)&Bs[buf][brow][bcol] = b2;
        }
        __syncthreads();
    }

#pragma unroll
    for (int ih = 0; ih < 2; ++ih) {
#pragma unroll
        for (int i = 0; i < 4; ++i) {
            int row = m0 + ih * 64 + ty * 4 + i;
            float* op = out + (size_t)row * Hd;
            int ii = ih * 4 + i;
            float4 v0 = make_float4(acc[ii][0], acc[ii][1], acc[ii][2], acc[ii][3]);
            float4 v1 = make_float4(acc[ii][4], acc[ii][5], acc[ii][6], acc[ii][7]);
            *(float4*)&op[tx * 4] = v0;
            *(float4*)&op[64 + tx * 4] = v1;
        }
    }
}

// ===========================================================================
// Kernel 2: flash attention on mma.sync tf32 (round-12 structure) with:
//  - K/V stored RAW fp32 in smem; tf32 hi/lo conversion at fragment-read
//    (halves LDS traffic; cvt rides the idle ALU pipe; identical math)
//  - cp.async double-buffered K/V prefetch (gmem latency hidden; 1 sync/tile)
//  - V read directly in gmem layout [key][h], stride 136 -> bank 8*tig+g,
//    conflict-free B-fragments, coalesced copy (old transpose removed)
// 256 thr = 4 q-groups x 2 key-halves; independent per-half online softmax,
// split-KV merge in epilogue. Pairing (x, 31-x): 33 BK=64 tiles per CTA.
// ===========================================================================
#define QKSTR 132   // Q/K row stride (floats): bank pattern 4g+tig, distinct
#define VSTR  136   // V row stride (floats): bank pattern 8*tig+g, distinct
#define PSTR  68    // P row stride

#define SM_Q  0                        // 64*132  = 8448  (raw fp32 Q)
#define SM_K0 (SM_Q + 64 * QKSTR)      // 8448    (raw K, buffer 0)
#define SM_V0 (SM_K0 + 64 * QKSTR)     // 16896   (raw V, buffer 0)
#define KVBUF (64 * QKSTR + 64 * VSTR) // 17152   (K+V pair size)
#define SM_P  (SM_K0 + 2 * KVBUF)      // 42752   64*68 = 4352
#define SM_MM (SM_P + 64 * PSTR)       // 47104
#define SM_LL (SM_MM + 64)             // 47168
#define ATTN_SMEM_FLOATS (SM_LL + 64)  // 47232 -> 188928 B
#define ATTN_SMEM_BYTES (ATTN_SMEM_FLOATS * 4)

__global__ __launch_bounds__(256, 1) void attn_kernel(float* __restrict__ out)
{
    extern __shared__ float sm[];
    float* Qs = sm + SM_Q;
    float* Ph = sm + SM_P;
    float* MM = sm + SM_MM;
    float* LL = sm + SM_LL;
    const uint32_t sb = smem_u32(sm);

    const int tid = threadIdx.x;
    const int w = tid >> 5;
    const int lane = tid & 31;
    const int g = lane >> 2;
    const int tig = lane & 3;
    const int qgrp = w & 3;
    const int khalf = w >> 2;
    const int kofs = 32 * khalf;
    const int b = blockIdx.y;
    const float scale = 45.25483399593904f;  // sqrt(2048)

    const int qrow0 = 16 * qgrp + g;
    const int aQ0 = qrow0 * QKSTR;
    const int aQ1 = (qrow0 + 8) * QKSTR;

    const float* Kgb = g_K + (size_t)(b * Tt) * Hd;
    const float* Vgb = g_V + (size_t)(b * Tt) * Hd;

    for (int half = 0; half < 2; ++half) {
        const int qt = half ? (31 - (int)blockIdx.x) : (int)blockIdx.x;

        __syncthreads();  // prior half fully done: Qs (epilogue buf) + K/V free

        // ---- prefetch K/V tile 0 into buffer 0 (raw, coalesced) ----
        {
            const float* Kg = Kgb;   // kt = 0
            const float* Vg = Vgb;
            const uint32_t kS = sb + SM_K0 * 4;
            const uint32_t vS = sb + SM_V0 * 4;
#pragma unroll
            for (int it = 0; it < 8; ++it) {
                int cid = it * 256 + tid;     // 2048 16B-chunks per tensor
                int r = cid >> 5;
                int c = (cid & 31) << 2;
                cp16(kS + (r * QKSTR + c) * 4, Kg + (size_t)r * Hd + c);
                cp16(vS + (r * VSTR + c) * 4, Vg + (size_t)r * Hd + c);
            }
            CP_COMMIT();
        }

        // ---- load Q tile [64][128] raw (plain loads overlap the cp.async) ----
        {
            const float* Qg = g_Q + ((size_t)(b * Tt) + qt * 64) * Hd;
#pragma unroll
            for (int it = 0; it < 8; ++it) {
                int fid = it * 256 + tid;
                int r = fid >> 5;
                int c = (fid & 31) << 2;
                *(float4*)&Qs[r * QKSTR + c] = *(const float4*)&Qg[(size_t)r * Hd + c];
            }
        }

        float m0 = -INFINITY, m1 = -INFINITY, l0 = 0.0f, l1 = 0.0f;
        float O[16][4];
#pragma unroll
        for (int a = 0; a < 16; ++a)
#pragma unroll
            for (int j = 0; j < 4; ++j) O[a][j] = 0.0f;

        for (int kt = 0; kt <= qt; ++kt) {
            const int bufi = kt & 1;
            const float* Ks = sm + SM_K0 + bufi * KVBUF;
            const float* Vs = sm + SM_V0 + bufi * KVBUF;

            CP_WAIT0();
            __syncthreads();   // tile kt visible to all; buffer bufi^1 free

            // ---- prefetch tile kt+1 into the other buffer ----
            if (kt < qt) {
                const float* Kg = Kgb + (size_t)(kt + 1) * 64 * Hd;
                const float* Vg = Vgb + (size_t)(kt + 1) * 64 * Hd;
                const uint32_t kS = sb + (SM_K0 + (bufi ^ 1) * KVBUF) * 4;
                const uint32_t vS = sb + (SM_V0 + (bufi ^ 1) * KVBUF) * 4;
#pragma unroll
                for (int it = 0; it < 8; ++it) {
                    int cid = it * 256 + tid;
                    int r = cid >> 5;
                    int c = (cid & 31) << 2;
                    cp16(kS + (r * QKSTR + c) * 4, Kg + (size_t)r * Hd + c);
                    cp16(vS + (r * VSTR + c) * 4, Vg + (size_t)r * Hd + c);
                }
                CP_COMMIT();
            }

            // ---- S = Q K^T on this warp's 32-key half (3 products),
            //      raw smem + on-the-fly tf32 hi/lo conversion ----
            float sc[4][4];
#pragma unroll
            for (int a = 0; a < 4; ++a)
#pragma unroll
                for (int j = 0; j < 4; ++j) sc[a][j] = 0.0f;

#pragma unroll
            for (int ks = 0; ks < 16; ++ks) {
                const int kb = ks * 8;
                float q0 = Qs[aQ0 + kb + tig];
                float q1 = Qs[aQ1 + kb + tig];
                float q2 = Qs[aQ0 + kb + tig + 4];
                float q3 = Qs[aQ1 + kb + tig + 4];
                float qh0 = tf32r(q0), qh1 = tf32r(q1), qh2 = tf32r(q2), qh3 = tf32r(q3);
                uint32_t ah0 = __float_as_uint(qh0);
                uint32_t ah1 = __float_as_uint(qh1);
                uint32_t ah2 = __float_as_uint(qh2);
                uint32_t ah3 = __float_as_uint(qh3);
                uint32_t al0 = __float_as_uint(tf32r(q0 - qh0));
                uint32_t al1 = __float_as_uint(tf32r(q1 - qh1));
                uint32_t al2 = __float_as_uint(tf32r(q2 - qh2));
                uint32_t al3 = __float_as_uint(tf32r(q3 - qh3));
#pragma unroll
                for (int a = 0; a < 4; ++a) {
                    const float* Kr = Ks + (kofs + 8 * a + g) * QKSTR + kb;
                    float k0 = Kr[tig];
                    float k1 = Kr[tig + 4];
                    float kh0 = tf32r(k0), kh1 = tf32r(k1);
                    uint32_t bh0 = __float_as_uint(kh0);
                    uint32_t bh1 = __float_as_uint(kh1);
                    uint32_t bl0 = __float_as_uint(tf32r(k0 - kh0));
                    uint32_t bl1 = __float_as_uint(tf32r(k1 - kh1));
                    mma8(sc[a], ah0, ah1, ah2, ah3, bh0, bh1);
                    mma8(sc[a], ah0, ah1, ah2, ah3, bl0, bl1);
                    mma8(sc[a], al0, al1, al2, al3, bh0, bh1);
                }
            }

            // ---- scale + causal mask ----
            const int qg0 = qt * 64 + qrow0;
            const int qg1 = qg0 + 8;
#pragma unroll
            for (int a = 0; a < 4; ++a) {
                const int col = kt * 64 + kofs + 8 * a + 2 * tig;
                sc[a][0] = (col     <= qg0) ? sc[a][0] * scale : -INFINITY;
                sc[a][1] = (col + 1 <= qg0) ? sc[a][1] * scale : -INFINITY;
                sc[a][2] = (col     <= qg1) ? sc[a][2] * scale : -INFINITY;
                sc[a][3] = (col + 1 <= qg1) ? sc[a][3] * scale : -INFINITY;
            }

            // ---- row maxima over this half (4-lane groups) ----
            float r0 = fmaxf(fmaxf(sc[0][0], sc[0][1]), fmaxf(sc[1][0], sc[1][1]));
            r0 = fmaxf(r0, fmaxf(fmaxf(sc[2][0], sc[2][1]), fmaxf(sc[3][0], sc[3][1])));
            float r1 = fmaxf(fmaxf(sc[0][2], sc[0][3]), fmaxf(sc[1][2], sc[1][3]));
            r1 = fmaxf(r1, fmaxf(fmaxf(sc[2][2], sc[2][3]), fmaxf(sc[3][2], sc[3][3])));
#pragma unroll
            for (int off = 1; off <= 2; off <<= 1) {
                r0 = fmaxf(r0, __shfl_xor_sync(0xffffffffu, r0, off));
                r1 = fmaxf(r1, __shfl_xor_sync(0xffffffffu, r1, off));
            }

            // ---- warp-local dead skip (contributions < e^-80 of final l) ----
            bool dead = (r0 <= m0 - 80.0f) && (r1 <= m1 - 80.0f);
            if (__all_sync(0xffffffffu, dead)) continue;

            // clamp so fully-masked rows never produce -inf - -inf = NaN
            float mn0 = fmaxf(fmaxf(m0, r0), -1e30f);
            float mn1 = fmaxf(fmaxf(m1, r1), -1e30f);
            float al_0 = __expf(m0 - mn0);
            float al_1 = __expf(m1 - mn1);
            float ls0 = 0.0f, ls1 = 0.0f;
#pragma unroll
            for (int a = 0; a < 4; ++a) {
                float p00 = __expf(sc[a][0] - mn0);
                float p01 = __expf(sc[a][1] - mn0);
                float p10 = __expf(sc[a][2] - mn1);
                float p11 = __expf(sc[a][3] - mn1);
                ls0 += p00 + p01;
                ls1 += p10 + p11;
                const int col = kofs + 8 * a + 2 * tig;
                Ph[qrow0 * PSTR + col] = tf32r(p00);
                Ph[qrow0 * PSTR + col + 1] = tf32r(p01);
                Ph[(qrow0 + 8) * PSTR + col] = tf32r(p10);
                Ph[(qrow0 + 8) * PSTR + col + 1] = tf32r(p11);
            }
#pragma unroll
            for (int off = 1; off <= 2; off <<= 1) {
                ls0 += __shfl_xor_sync(0xffffffffu, ls0, off);
                ls1 += __shfl_xor_sync(0xffffffffu, ls1, off);
            }
            l0 = l0 * al_0 + ls0;
            l1 = l1 * al_1 + ls1;
            m0 = mn0;
            m1 = mn1;

#pragma unroll
            for (int a = 0; a < 16; ++a) {
                O[a][0] *= al_0; O[a][1] *= al_0;
                O[a][2] *= al_1; O[a][3] *= al_1;
            }

            __syncwarp();  // P block is warp-private; order STS before LDS

            // ---- O_half += P(:, half) V(half, :) — raw V, cvt at read ----
#pragma unroll
            for (int ks = 0; ks < 4; ++ks) {
                const int kb = kofs + ks * 8;
                uint32_t a0 = __float_as_uint(Ph[qrow0 * PSTR + kb + tig]);
                uint32_t a1 = __float_as_uint(Ph[(qrow0 + 8) * PSTR + kb + tig]);
                uint32_t a2 = __float_as_uint(Ph[qrow0 * PSTR + kb + tig + 4]);
                uint32_t a3 = __float_as_uint(Ph[(qrow0 + 8) * PSTR + kb + tig + 4]);
                const float* Vr0 = Vs + (kb + tig) * VSTR;
                const float* Vr1 = Vs + (kb + tig + 4) * VSTR;
#pragma unroll
                for (int a = 0; a < 16; ++a) {
                    const int hc = 8 * a + g;
                    uint32_t bh0 = __float_as_uint(tf32r(Vr0[hc]));
                    uint32_t bh1 = __float_as_uint(tf32r(Vr1[hc]));
                    mma8(O[a], a0, a1, a2, a3, bh0, bh1);
                }
            }
        }

        // ---- epilogue: split-KV merge of the two key-halves ----
        __syncthreads();           // mainloop reads of Qs done
        float* Obuf = Qs;          // reuse [64][132]
        if (khalf == 1) {
#pragma unroll
            for (int a = 0; a < 16; ++a) {
                const int colc = 8 * a + 2 * tig;
                *(float2*)&Obuf[qrow0 * QKSTR + colc] = make_float2(O[a][0], O[a][1]);
                *(float2*)&Obuf[(qrow0 + 8) * QKSTR + colc] = make_float2(O[a][2], O[a][3]);
            }
            if (tig == 0) {
                MM[qrow0] = m0; LL[qrow0] = l0;
                MM[qrow0 + 8] = m1; LL[qrow0 + 8] = l1;
            }
        }
        __syncthreads();
        if (khalf == 0) {
            const float m1r = MM[qrow0],     l1r = LL[qrow0];
            const float m3r = MM[qrow0 + 8], l3r = LL[qrow0 + 8];
            const float mf0 = fmaxf(m0, m1r);
            const float mf1 = fmaxf(m1, m3r);
            const float w00 = __expf(m0 - mf0), w01 = __expf(m1r - mf0);
            const float w10 = __expf(m1 - mf1), w11 = __expf(m3r - mf1);
            const float inv0 = 1.0f / (l0 * w00 + l1r * w01);
            const float inv1 = 1.0f / (l1 * w10 + l3r * w11);
            const int q0 = qt * 64 + qrow0;
            float* op0 = out + ((size_t)(b * Tt) + q0) * Hd;
            float* op1 = op0 + 8 * Hd;
#pragma unroll
            for (int a = 0; a < 16; ++a) {
                const int colc = 8 * a + 2 * tig;
                float2 e0 = *(float2*)&Obuf[qrow0 * QKSTR + colc];
                float2 e1 = *(float2*)&Obuf[(qrow0 + 8) * QKSTR + colc];
                *(float2*)&op0[colc] =
                    make_float2((O[a][0] * w00 + e0.x * w01) * inv0,
                                (O[a][1] * w00 + e0.y * w01) * inv0);
                *(float2*)&op1[colc] =
                    make_float2((O[a][2] * w10 + e1.x * w11) * inv1,
                                (O[a][3] * w10 + e1.y * w11) * inv1);
            }
        }
    }
}

// ===========================================================================

extern "C" void kernel_launch(void* const* d_in, const int* in_sizes, int n_in,
                              void* d_out, int out_size)
{
    const float* x  = (const float*)d_in[0];
    const float* Wq = (const float*)d_in[1];
    const float* Wk = (const float*)d_in[2];
    const float* Wv = (const float*)d_in[3];
    float* out = (float*)d_out;

    dim3 g1(NROW / 128, 3);
    qkv_kernel<<<g1, 256>>>(x, Wq, Wk, Wv);

    cudaFuncSetAttribute(attn_kernel, cudaFuncAttributeMaxDynamicSharedMemorySize,
                         ATTN_SMEM_BYTES);
    dim3 g2(16, Bb);
    attn_kernel<<<g2, 256, ATTN_SMEM_BYTES>>>(out);
}

// round 15
// speedup vs baseline: 1.2987x; 1.0094x over previous
#include <cuda_runtime.h>
#include <cstdint>
#include <math.h>

#define Bb 8
#define Tt 2048
#define Ee 1024
#define Hd 128
#define NROW (Bb * Tt)

// Scratch (__device__ globals per allocation rules).
__device__ float g_Q[NROW * Hd];
__device__ float g_K[NROW * Hd];
__device__ float g_V[NROW * Hd];

__device__ __forceinline__ float tf32r(float x) {
    float r;
    asm("cvt.rna.tf32.f32 %0, %1;" : "=f"(r) : "f"(x));
    return r;
}

// mma.sync m16n8k8 tf32: D = A*B + C (C==D registers)
__device__ __forceinline__ void mma8(float c[4], uint32_t a0, uint32_t a1,
                                     uint32_t a2, uint32_t a3,
                                     uint32_t b0, uint32_t b1) {
    asm volatile(
        "mma.sync.aligned.m16n8k8.row.col.f32.tf32.tf32.f32 "
        "{%0,%1,%2,%3}, {%4,%5,%6,%7}, {%8,%9}, {%0,%1,%2,%3};"
        : "+f"(c[0]), "+f"(c[1]), "+f"(c[2]), "+f"(c[3])
        : "r"(a0), "r"(a1), "r"(a2), "r"(a3), "r"(b0), "r"(b1));
}

__device__ __forceinline__ uint32_t smem_u32(const void* p) {
    uint32_t a;
    asm("{ .reg .u64 t; cvta.to.shared.u64 t, %1; cvt.u32.u64 %0, t; }"
        : "=r"(a) : "l"(p));
    return a;
}
__device__ __forceinline__ void cp16(uint32_t saddr, const void* g) {
    asm volatile("cp.async.cg.shared.global [%0], [%1], 16;"
                 :: "r"(saddr), "l"(g) : "memory");
}
#define CP_COMMIT() asm volatile("cp.async.commit_group;" ::: "memory")
#define CP_WAIT0()  asm volatile("cp.async.wait_group 0;" ::: "memory")

// ===========================================================================
// Kernel 1: QKV projection, fp32 (proven, ~96% of FFMA ceiling).
// ===========================================================================
__global__ __launch_bounds__(256, 2) void qkv_kernel(
    const float* __restrict__ x,
    const float* __restrict__ Wq,
    const float* __restrict__ Wk,
    const float* __restrict__ Wv)
{
    __shared__ float As[2][8][128];
    __shared__ float Bs[2][8][128];

    const int which = blockIdx.y;
    const float* __restrict__ W = (which == 0) ? Wq : ((which == 1) ? Wk : Wv);
    float* __restrict__ out = (which == 0) ? g_Q : ((which == 1) ? g_K : g_V);

    const int tid = threadIdx.x;
    const int tx = tid & 15;
    const int ty = tid >> 4;
    const int m0 = blockIdx.x * 128;

    const int arow = tid >> 1;
    const int acol = (tid & 1) * 4;
    const int brow = tid >> 5;
    const int bcol = (tid & 31) * 4;

    const float* xg = x + (size_t)(m0 + arow) * Ee + acol;
    const float* wg = W + (size_t)brow * Hd + bcol;

    float acc[8][8];
#pragma unroll
    for (int i = 0; i < 8; ++i)
#pragma unroll
        for (int j = 0; j < 8; ++j) acc[i][j] = 0.0f;

    {
        float4 a = *(const float4*)xg;
        float4 bv = *(const float4*)wg;
        As[0][acol + 0][arow] = a.x;
        As[0][acol + 1][arow] = a.y;
        As[0][acol + 2][arow] = a.z;
        As[0][acol + 3][arow] = a.w;
        *(float4*)&Bs[0][brow][bcol] = bv;
    }
    __syncthreads();

    int buf = 0;
    const int NT = Ee / 8;
    for (int t = 0; t < NT; ++t) {
        float4 a2, b2;
        if (t < NT - 1) {
            a2 = *(const float4*)(xg + (size_t)(t + 1) * 8);
            b2 = *(const float4*)(wg + (size_t)(t + 1) * 8 * Hd);
        }
#pragma unroll
        for (int k = 0; k < 8; ++k) {
            float4 a0 = *(const float4*)&As[buf][k][ty * 4];
            float4 a1 = *(const float4*)&As[buf][k][64 + ty * 4];
            float4 b0 = *(const float4*)&Bs[buf][k][tx * 4];
            float4 b1 = *(const float4*)&Bs[buf][k][64 + tx * 4];
            float af[8] = {a0.x, a0.y, a0.z, a0.w, a1.x, a1.y, a1.z, a1.w};
            float bf[8] = {b0.x, b0.y, b0.z, b0.w, b1.x, b1.y, b1.z, b1.w};
#pragma unroll
            for (int i = 0; i < 8; ++i)
#pragma unroll
                for (int j = 0; j < 8; ++j)
                    acc[i][j] = fmaf(af[i], bf[j], acc[i][j]);
        }
        if (t < NT - 1) {
            buf ^= 1;
            As[buf][acol + 0][arow] = a2.x;
            As[buf][acol + 1][arow] = a2.y;
            As[buf][acol + 2][arow] = a2.z;
            As[buf][acol + 3][arow] = a2.w;
            *(float4*)&Bs[buf][brow][bcol] = b2;
        }
        __syncthreads();
    }

#pragma unroll
    for (int ih = 0; ih < 2; ++ih) {
#pragma unroll
        for (int i = 0; i < 4; ++i) {
            int row = m0 + ih * 64 + ty * 4 + i;
            float* op = out + (size_t)row * Hd;
            int ii = ih * 4 + i;
            float4 v0 = make_float4(acc[ii][0], acc[ii][1], acc[ii][2], acc[ii][3]);
            float4 v1 = make_float4(acc[ii][4], acc[ii][5], acc[ii][6], acc[ii][7]);
            *(float4*)&op[tx * 4] = v0;
            *(float4*)&op[64 + tx * 4] = v1;
        }
    }
}

// ===========================================================================
// Kernel 2: flash attention on mma.sync tf32 (round-14 structure) with
// COOPERATIVE K/V CONVERSION: after each tile's cp.async lands, all 256
// threads convert K raw -> hi (in place) + lo (single Kl plane) and
// V raw -> hi (in place), each element ONCE per CTA (was 4x per warp-group
// at fragment read). S and PV loops then do zero conversion ALU for K/V.
// Q stays raw with cvt-at-read (not redundant; smem budget).
// 256 thr = 4 q-groups x 2 key-halves; independent per-half online softmax,
// split-KV merge in epilogue. Pairing (x, 31-x): 33 BK=64 tiles per CTA.
// ===========================================================================
#define QKSTR 132   // Q/K row stride (floats)
#define VSTR  136   // V row stride (floats): bank pattern 8*tig+g, distinct
#define PSTR  68    // P row stride

#define SM_Q  0                        // 64*132 = 8448  (raw fp32 Q)
#define SM_K0 (SM_Q + 64 * QKSTR)      // 8448   (K raw->hi, buffer 0)
#define SM_V0 (SM_K0 + 64 * QKSTR)     // 16896  (V raw->hi, buffer 0)
#define KVBUF (64 * QKSTR + 64 * VSTR) // 17152
#define SM_KL (SM_K0 + 2 * KVBUF)      // 42752  (K lo plane, single buffer)
#define SM_P  (SM_KL + 64 * QKSTR)     // 51200  64*68 = 4352
#define SM_MM (SM_P + 64 * PSTR)       // 55552
#define SM_LL (SM_MM + 64)             // 55616
#define ATTN_SMEM_FLOATS (SM_LL + 64)  // 55680 -> 222720 B
#define ATTN_SMEM_BYTES (ATTN_SMEM_FLOATS * 4)

__global__ __launch_bounds__(256, 1) void attn_kernel(float* __restrict__ out)
{
    extern __shared__ float sm[];
    float* Qs = sm + SM_Q;
    float* Kls = sm + SM_KL;
    float* Ph = sm + SM_P;
    float* MM = sm + SM_MM;
    float* LL = sm + SM_LL;
    const uint32_t sb = smem_u32(sm);

    const int tid = threadIdx.x;
    const int w = tid >> 5;
    const int lane = tid & 31;
    const int g = lane >> 2;
    const int tig = lane & 3;
    const int qgrp = w & 3;
    const int khalf = w >> 2;
    const int kofs = 32 * khalf;
    const int b = blockIdx.y;
    const float scale = 45.25483399593904f;  // sqrt(2048)

    const int qrow0 = 16 * qgrp + g;
    const int aQ0 = qrow0 * QKSTR;
    const int aQ1 = (qrow0 + 8) * QKSTR;

    const float* Kgb = g_K + (size_t)(b * Tt) * Hd;
    const float* Vgb = g_V + (size_t)(b * Tt) * Hd;

    for (int half = 0; half < 2; ++half) {
        const int qt = half ? (31 - (int)blockIdx.x) : (int)blockIdx.x;

        __syncthreads();  // prior half fully done: Qs (epilogue buf) + K/V free

        // ---- prefetch K/V tile 0 into buffer 0 (raw, coalesced) ----
        {
            const uint32_t kS = sb + SM_K0 * 4;
            const uint32_t vS = sb + SM_V0 * 4;
#pragma unroll
            for (int it = 0; it < 8; ++it) {
                int cid = it * 256 + tid;
                int r = cid >> 5;
                int c = (cid & 31) << 2;
                cp16(kS + (r * QKSTR + c) * 4, Kgb + (size_t)r * Hd + c);
                cp16(vS + (r * VSTR + c) * 4, Vgb + (size_t)r * Hd + c);
            }
            CP_COMMIT();
        }

        // ---- load Q tile [64][128] raw (plain loads overlap the cp.async) ----
        {
            const float* Qg = g_Q + ((size_t)(b * Tt) + qt * 64) * Hd;
#pragma unroll
            for (int it = 0; it < 8; ++it) {
                int fid = it * 256 + tid;
                int r = fid >> 5;
                int c = (fid & 31) << 2;
                *(float4*)&Qs[r * QKSTR + c] = *(const float4*)&Qg[(size_t)r * Hd + c];
            }
        }

        float m0 = -INFINITY, m1 = -INFINITY, l0 = 0.0f, l1 = 0.0f;
        float O[16][4];
#pragma unroll
        for (int a = 0; a < 16; ++a)
#pragma unroll
            for (int j = 0; j < 4; ++j) O[a][j] = 0.0f;

        for (int kt = 0; kt <= qt; ++kt) {
            const int bufi = kt & 1;
            float* Ks = sm + SM_K0 + bufi * KVBUF;
            float* Vs = sm + SM_V0 + bufi * KVBUF;

            CP_WAIT0();
            __syncthreads();   // tile kt raw data visible; other buffer free

            // ---- prefetch tile kt+1 into the other buffer ----
            if (kt < qt) {
                const float* Kg = Kgb + (size_t)(kt + 1) * 64 * Hd;
                const float* Vg = Vgb + (size_t)(kt + 1) * 64 * Hd;
                const uint32_t kS = sb + (SM_K0 + (bufi ^ 1) * KVBUF) * 4;
                const uint32_t vS = sb + (SM_V0 + (bufi ^ 1) * KVBUF) * 4;
#pragma unroll
                for (int it = 0; it < 8; ++it) {
                    int cid = it * 256 + tid;
                    int r = cid >> 5;
                    int c = (cid & 31) << 2;
                    cp16(kS + (r * QKSTR + c) * 4, Kg + (size_t)r * Hd + c);
                    cp16(vS + (r * VSTR + c) * 4, Vg + (size_t)r * Hd + c);
                }
                CP_COMMIT();
            }

            // ---- cooperative conversion: each element once per CTA ----
            // K: hi in place + lo into Kls;  V: hi in place.
#pragma unroll
            for (int it = 0; it < 8; ++it) {
                int cid = it * 256 + tid;
                int r = cid >> 5;
                int c = (cid & 31) << 2;
                {
                    float4 v = *(float4*)&Ks[r * QKSTR + c];
                    float4 hi = make_float4(tf32r(v.x), tf32r(v.y), tf32r(v.z), tf32r(v.w));
                    float4 lo = make_float4(tf32r(v.x - hi.x), tf32r(v.y - hi.y),
                                            tf32r(v.z - hi.z), tf32r(v.w - hi.w));
                    *(float4*)&Ks[r * QKSTR + c] = hi;
                    *(float4*)&Kls[r * QKSTR + c] = lo;
                }
                {
                    float4 v = *(float4*)&Vs[r * VSTR + c];
                    float4 hi = make_float4(tf32r(v.x), tf32r(v.y), tf32r(v.z), tf32r(v.w));
                    *(float4*)&Vs[r * VSTR + c] = hi;
                }
            }
            __syncthreads();   // converted tile visible to all warps

            // ---- S = Q K^T on this warp's 32-key half (3 products) ----
            float sc[4][4];
#pragma unroll
            for (int a = 0; a < 4; ++a)
#pragma unroll
                for (int j = 0; j < 4; ++j) sc[a][j] = 0.0f;

#pragma unroll
            for (int ks = 0; ks < 16; ++ks) {
                const int kb = ks * 8;
                float q0 = Qs[aQ0 + kb + tig];
                float q1 = Qs[aQ1 + kb + tig];
                float q2 = Qs[aQ0 + kb + tig + 4];
                float q3 = Qs[aQ1 + kb + tig + 4];
                float qh0 = tf32r(q0), qh1 = tf32r(q1), qh2 = tf32r(q2), qh3 = tf32r(q3);
                uint32_t ah0 = __float_as_uint(qh0);
                uint32_t ah1 = __float_as_uint(qh1);
                uint32_t ah2 = __float_as_uint(qh2);
                uint32_t ah3 = __float_as_uint(qh3);
                uint32_t al0 = __float_as_uint(tf32r(q0 - qh0));
                uint32_t al1 = __float_as_uint(tf32r(q1 - qh1));
                uint32_t al2 = __float_as_uint(tf32r(q2 - qh2));
                uint32_t al3 = __float_as_uint(tf32r(q3 - qh3));
#pragma unroll
                for (int a = 0; a < 4; ++a) {
                    const int kr = (kofs + 8 * a + g) * QKSTR + kb;
                    uint32_t bh0 = __float_as_uint(Ks[kr + tig]);
                    uint32_t bh1 = __float_as_uint(Ks[kr + tig + 4]);
                    uint32_t bl0 = __float_as_uint(Kls[kr + tig]);
                    uint32_t bl1 = __float_as_uint(Kls[kr + tig + 4]);
                    mma8(sc[a], ah0, ah1, ah2, ah3, bh0, bh1);
                    mma8(sc[a], ah0, ah1, ah2, ah3, bl0, bl1);
                    mma8(sc[a], al0, al1, al2, al3, bh0, bh1);
                }
            }

            // ---- scale + causal mask ----
            const int qg0 = qt * 64 + qrow0;
            const int qg1 = qg0 + 8;
#pragma unroll
            for (int a = 0; a < 4; ++a) {
                const int col = kt * 64 + kofs + 8 * a + 2 * tig;
                sc[a][0] = (col     <= qg0) ? sc[a][0] * scale : -INFINITY;
                sc[a][1] = (col + 1 <= qg0) ? sc[a][1] * scale : -INFINITY;
                sc[a][2] = (col     <= qg1) ? sc[a][2] * scale : -INFINITY;
                sc[a][3] = (col + 1 <= qg1) ? sc[a][3] * scale : -INFINITY;
            }

            // ---- row maxima over this half (4-lane groups) ----
            float r0 = fmaxf(fmaxf(sc[0][0], sc[0][1]), fmaxf(sc[1][0], sc[1][1]));
            r0 = fmaxf(r0, fmaxf(fmaxf(sc[2][0], sc[2][1]), fmaxf(sc[3][0], sc[3][1])));
            float r1 = fmaxf(fmaxf(sc[0][2], sc[0][3]), fmaxf(sc[1][2], sc[1][3]));
            r1 = fmaxf(r1, fmaxf(fmaxf(sc[2][2], sc[2][3]), fmaxf(sc[3][2], sc[3][3])));
#pragma unroll
            for (int off = 1; off <= 2; off <<= 1) {
                r0 = fmaxf(r0, __shfl_xor_sync(0xffffffffu, r0, off));
                r1 = fmaxf(r1, __shfl_xor_sync(0xffffffffu, r1, off));
            }

            // ---- warp-local dead skip (contributions < e^-80 of final l) ----
            bool dead = (r0 <= m0 - 80.0f) && (r1 <= m1 - 80.0f);
            if (__all_sync(0xffffffffu, dead)) continue;

            // clamp so fully-masked rows never produce -inf - -inf = NaN
            float mn0 = fmaxf(fmaxf(m0, r0), -1e30f);
            float mn1 = fmaxf(fmaxf(m1, r1), -1e30f);
            float al_0 = __expf(m0 - mn0);
            float al_1 = __expf(m1 - mn1);
            float ls0 = 0.0f, ls1 = 0.0f;
#pragma unroll
            for (int a = 0; a < 4; ++a) {
                float p00 = __expf(sc[a][0] - mn0);
                float p01 = __expf(sc[a][1] - mn0);
                float p10 = __expf(sc[a][2] - mn1);
                float p11 = __expf(sc[a][3] - mn1);
                ls0 += p00 + p01;
                ls1 += p10 + p11;
                const int col = kofs + 8 * a + 2 * tig;
                Ph[qrow0 * PSTR + col] = tf32r(p00);
                Ph[qrow0 * PSTR + col + 1] = tf32r(p01);
                Ph[(qrow0 + 8) * PSTR + col] = tf32r(p10);
                Ph[(qrow0 + 8) * PSTR + col + 1] = tf32r(p11);
            }
#pragma unroll
            for (int off = 1; off <= 2; off <<= 1) {
                ls0 += __shfl_xor_sync(0xffffffffu, ls0, off);
                ls1 += __shfl_xor_sync(0xffffffffu, ls1, off);
            }
            l0 = l0 * al_0 + ls0;
            l1 = l1 * al_1 + ls1;
            m0 = mn0;
            m1 = mn1;

#pragma unroll
            for (int a = 0; a < 16; ++a) {
                O[a][0] *= al_0; O[a][1] *= al_0;
                O[a][2] *= al_1; O[a][3] *= al_1;
            }

            __syncwarp();  // P block is warp-private; order STS before LDS

            // ---- O_half += P(:, half) V(half, :) — V pre-converted ----
#pragma unroll
            for (int ks = 0; ks < 4; ++ks) {
                const int kb = kofs + ks * 8;
                uint32_t a0 = __float_as_uint(Ph[qrow0 * PSTR + kb + tig]);
                uint32_t a1 = __float_as_uint(Ph[(qrow0 + 8) * PSTR + kb + tig]);
                uint32_t a2 = __float_as_uint(Ph[qrow0 * PSTR + kb + tig + 4]);
                uint32_t a3 = __float_as_uint(Ph[(qrow0 + 8) * PSTR + kb + tig + 4]);
                const float* Vr0 = Vs + (kb + tig) * VSTR;
                const float* Vr1 = Vs + (kb + tig + 4) * VSTR;
#pragma unroll
                for (int a = 0; a < 16; ++a) {
                    const int hc = 8 * a + g;
                    uint32_t bh0 = __float_as_uint(Vr0[hc]);
                    uint32_t bh1 = __float_as_uint(Vr1[hc]);
                    mma8(O[a], a0, a1, a2, a3, bh0, bh1);
                }
            }
        }

        // ---- epilogue: split-KV merge of the two key-halves ----
        __syncthreads();           // mainloop reads of Qs done
        float* Obuf = Qs;          // reuse [64][132]
        if (khalf == 1) {
#pragma unroll
            for (int a = 0; a < 16; ++a) {
                const int colc = 8 * a + 2 * tig;
                *(float2*)&Obuf[qrow0 * QKSTR + colc] = make_float2(O[a][0], O[a][1]);
                *(float2*)&Obuf[(qrow0 + 8) * QKSTR + colc] = make_float2(O[a][2], O[a][3]);
            }
            if (tig == 0) {
                MM[qrow0] = m0; LL[qrow0] = l0;
                MM[qrow0 + 8] = m1; LL[qrow0 + 8] = l1;
            }
        }
        __syncthreads();
        if (khalf == 0) {
            const float m1r = MM[qrow0],     l1r = LL[qrow0];
            const float m3r = MM[qrow0 + 8], l3r = LL[qrow0 + 8];
            const float mf0 = fmaxf(m0, m1r);
            const float mf1 = fmaxf(m1, m3r);
            const float w00 = __expf(m0 - mf0), w01 = __expf(m1r - mf0);
            const float w10 = __expf(m1 - mf1), w11 = __expf(m3r - mf1);
            const float inv0 = 1.0f / (l0 * w00 + l1r * w01);
            const float inv1 = 1.0f / (l1 * w10 + l3r * w11);
            const int q0 = qt * 64 + qrow0;
            float* op0 = out + ((size_t)(b * Tt) + q0) * Hd;
            float* op1 = op0 + 8 * Hd;
#pragma unroll
            for (int a = 0; a < 16; ++a) {
                const int colc = 8 * a + 2 * tig;
                float2 e0 = *(float2*)&Obuf[qrow0 * QKSTR + colc];
                float2 e1 = *(float2*)&Obuf[(qrow0 + 8) * QKSTR + colc];
                *(float2*)&op0[colc] =
                    make_float2((O[a][0] * w00 + e0.x * w01) * inv0,
                                (O[a][1] * w00 + e0.y * w01) * inv0);
                *(float2*)&op1[colc] =
                    make_float2((O[a][2] * w10 + e1.x * w11) * inv1,
                                (O[a][3] * w10 + e1.y * w11) * inv1);
            }
        }
    }
}

// ===========================================================================

extern "C" void kernel_launch(void* const* d_in, const int* in_sizes, int n_in,
                              void* d_out, int out_size)
{
    const float* x  = (const float*)d_in[0];
    const float* Wq = (const float*)d_in[1];
    const float* Wk = (const float*)d_in[2];
    const float* Wv = (const float*)d_in[3];
    float* out = (float*)d_out;

    dim3 g1(NROW / 128, 3);
    qkv_kernel<<<g1, 256>>>(x, Wq, Wk, Wv);

    cudaFuncSetAttribute(attn_kernel, cudaFuncAttributeMaxDynamicSharedMemorySize,
                         ATTN_SMEM_BYTES);
    dim3 g2(16, Bb);
    attn_kernel<<<g2, 256, ATTN_SMEM_BYTES>>>(out);
}